// round 1
// baseline (speedup 1.0000x reference)
#include <cuda_runtime.h>
#include <cuda_bf16.h>

#define N_NODES 100000
#define E_EDGES 1600000
#define IN_DIM 32
#define HID 64
#define NHEADS 2
#define F1 128   // NHEADS*HID
#define OUTC 64

// ---------------- scratch (device globals; no allocation allowed) ------------
__device__ __align__(16) float g_h1 [(size_t)N_NODES * F1];
__device__ __align__(16) float g_acc1[(size_t)N_NODES * F1];
__device__ __align__(16) float g_hln[(size_t)N_NODES * F1];
__device__ __align__(16) float g_h2 [(size_t)N_NODES * OUTC];
__device__ __align__(16) float g_acc2[(size_t)N_NODES * OUTC];
__device__ float g_as1[N_NODES * NHEADS];
__device__ float g_ad1[N_NODES * NHEADS];
__device__ float g_esum1[N_NODES * NHEADS];
__device__ float g_as2[N_NODES];
__device__ float g_ad2[N_NODES];
__device__ float g_esum2[N_NODES];
__device__ float g_was1[IN_DIM * NHEADS];
__device__ float g_wad1[IN_DIM * NHEADS];
__device__ float g_was2[F1];
__device__ float g_wad2[F1];

__device__ __forceinline__ float lrelu(float v) { return v > 0.f ? v : 0.2f * v; }

__device__ __forceinline__ void red_add_v4(float* addr, float a, float b, float c, float d) {
    asm volatile("red.global.add.v4.f32 [%0], {%1,%2,%3,%4};"
                 :: "l"(addr), "f"(a), "f"(b), "f"(c), "f"(d) : "memory");
}

// ---------------- fold attention vectors into the linear weights -------------
// w_as1[k][h] = sum_c W1[k][h*HID+c] * att_src1[h][c]   (so a_s = x @ w_as1)
__global__ void k_fold(const float* __restrict__ W1,
                       const float* __restrict__ as1, const float* __restrict__ ad1,
                       const float* __restrict__ W2,
                       const float* __restrict__ as2, const float* __restrict__ ad2) {
    int t = threadIdx.x;  // 128 threads
    if (t < IN_DIM * NHEADS) {
        int k = t & (IN_DIM - 1), h = t >> 5;
        float s = 0.f, d = 0.f;
        for (int c = 0; c < HID; ++c) {
            float w = W1[k * F1 + h * HID + c];
            s += w * as1[h * HID + c];
            d += w * ad1[h * HID + c];
        }
        g_was1[k * NHEADS + h] = s;
        g_wad1[k * NHEADS + h] = d;
    }
    if (t < F1) {
        float s = 0.f, d = 0.f;
        for (int c = 0; c < OUTC; ++c) {
            float w = W2[t * OUTC + c];
            s += w * as2[c];
            d += w * ad2[c];
        }
        g_was2[t] = s;
        g_wad2[t] = d;
    }
}

// ---------------- layer-1 projection: h1 = x @ W1, plus logits ---------------
__global__ void k1_proj(const float* __restrict__ x, const float* __restrict__ W1, int n) {
    __shared__ float Ws[IN_DIM * F1];       // 16 KB
    __shared__ float xs[8][IN_DIM];         // 1 KB
    int t = threadIdx.x;                    // 256 threads
    for (int i = t; i < IN_DIM * F1; i += 256) Ws[i] = W1[i];
    int base = blockIdx.x * 8;
    {
        int nn = base + (t >> 5);
        if (nn < n) xs[t >> 5][t & 31] = x[(size_t)nn * IN_DIM + (t & 31)];
    }
    __syncthreads();
    int j = t & (F1 - 1);
    int s0 = t >> 7;  // 0..1
    for (int p = 0; p < 4; ++p) {
        int slot = s0 + p * 2;
        int nn = base + slot;
        if (nn >= n) continue;
        float acc = 0.f;
        #pragma unroll
        for (int k = 0; k < IN_DIM; ++k) acc += xs[slot][k] * Ws[k * F1 + j];
        g_h1[(size_t)nn * F1 + j] = acc;
        if (j < 4) {
            const float* wv = (j < 2) ? g_was1 : g_wad1;
            int h = j & 1;
            float a = 0.f;
            #pragma unroll
            for (int k = 0; k < IN_DIM; ++k) a += xs[slot][k] * wv[k * NHEADS + h];
            if (j < 2) g_as1[nn * NHEADS + h] = a;
            else       g_ad1[nn * NHEADS + h] = a;
        }
    }
}

// ---------------- layer-1 edge aggregation (warp per edge) -------------------
__global__ void k2_edge1(const int* __restrict__ src, const int* __restrict__ dst, int E) {
    int gid = blockIdx.x * blockDim.x + threadIdx.x;
    int e = gid >> 5;
    if (e >= E) return;
    int lane = gid & 31;
    int s = __ldg(&src[e]);
    int d = __ldg(&dst[e]);
    int h = lane >> 4;
    float ev = g_as1[s * NHEADS + h] + g_ad1[d * NHEADS + h];
    float w = __expf(lrelu(ev));
    if ((lane & 15) == 0) atomicAdd(&g_esum1[d * NHEADS + h], w);
    int off = lane * 4;  // 0..124, head boundary at 64 matches lane>>4
    const float4 v = *reinterpret_cast<const float4*>(&g_h1[(size_t)s * F1 + off]);
    red_add_v4(&g_acc1[(size_t)d * F1 + off], w * v.x, w * v.y, w * v.z, w * v.w);
}

// ---------------- layer-1 finalize: self-loop + normalize + LN + ReLU --------
__global__ void k3_finalize1(const float* __restrict__ bias1,
                             const float* __restrict__ gamma,
                             const float* __restrict__ beta) {
    int n = blockIdx.x;
    int t = threadIdx.x;  // 128
    int h = t >> 6;
    float wself = __expf(lrelu(g_as1[n * NHEADS + h] + g_ad1[n * NHEADS + h]));
    float denom = g_esum1[n * NHEADS + h] + wself;
    size_t idx = (size_t)n * F1 + t;
    float val = (g_acc1[idx] + wself * g_h1[idx]) / denom + bias1[t];

    __shared__ float sh[4];
    float sum = val;
    #pragma unroll
    for (int o = 16; o > 0; o >>= 1) sum += __shfl_xor_sync(0xffffffffu, sum, o);
    if ((t & 31) == 0) sh[t >> 5] = sum;
    __syncthreads();
    float mu = (sh[0] + sh[1] + sh[2] + sh[3]) * (1.f / 128.f);
    float dv = val - mu;
    __syncthreads();
    float s2 = dv * dv;
    #pragma unroll
    for (int o = 16; o > 0; o >>= 1) s2 += __shfl_xor_sync(0xffffffffu, s2, o);
    if ((t & 31) == 0) sh[t >> 5] = s2;
    __syncthreads();
    float var = (sh[0] + sh[1] + sh[2] + sh[3]) * (1.f / 128.f);
    float y = dv * rsqrtf(var + 1e-5f) * gamma[t] + beta[t];
    g_hln[idx] = y > 0.f ? y : 0.f;
}

// ---------------- layer-2 projection: h2 = hln @ W2, plus logits -------------
__global__ void k4_proj2(const float* __restrict__ W2, int n) {
    __shared__ float Ws[F1 * OUTC];   // 32 KB
    __shared__ float xs[16][F1];      // 8 KB
    int t = threadIdx.x;              // 256
    for (int i = t; i < F1 * OUTC; i += 256) Ws[i] = W2[i];
    int base = blockIdx.x * 16;
    for (int i = t; i < 16 * F1 / 4; i += 256) {
        int slot = i / (F1 / 4), k4 = i % (F1 / 4);
        int nn = base + slot;
        float4 v = (nn < n) ? *reinterpret_cast<const float4*>(&g_hln[(size_t)nn * F1 + k4 * 4])
                            : make_float4(0.f, 0.f, 0.f, 0.f);
        *reinterpret_cast<float4*>(&xs[slot][k4 * 4]) = v;
    }
    __syncthreads();
    int j = t & (OUTC - 1);
    int s0 = t >> 6;  // 0..3
    for (int p = 0; p < 4; ++p) {
        int slot = s0 * 4 + p;
        int nn = base + slot;
        if (nn >= n) continue;
        float acc = 0.f;
        #pragma unroll
        for (int k = 0; k < F1; ++k) acc += xs[slot][k] * Ws[k * OUTC + j];
        g_h2[(size_t)nn * OUTC + j] = acc;
        if (j < 2) {
            const float* wv = (j == 0) ? g_was2 : g_wad2;
            float a = 0.f;
            #pragma unroll
            for (int k = 0; k < F1; ++k) a += xs[slot][k] * wv[k];
            if (j == 0) g_as2[nn] = a;
            else        g_ad2[nn] = a;
        }
    }
}

// ---------------- layer-2 edge aggregation (16 threads per edge) -------------
__global__ void k5_edge2(const int* __restrict__ src, const int* __restrict__ dst, int E) {
    int gid = blockIdx.x * blockDim.x + threadIdx.x;
    int e = gid >> 4;
    if (e >= E) return;
    int lane = gid & 15;
    int s = __ldg(&src[e]);
    int d = __ldg(&dst[e]);
    float w = __expf(lrelu(g_as2[s] + g_ad2[d]));
    if (lane == 0) atomicAdd(&g_esum2[d], w);
    const float4 v = *reinterpret_cast<const float4*>(&g_h2[(size_t)s * OUTC + lane * 4]);
    red_add_v4(&g_acc2[(size_t)d * OUTC + lane * 4], w * v.x, w * v.y, w * v.z, w * v.w);
}

// ---------------- layer-2 finalize --------------------------------------------
__global__ void k6_finalize2(float* __restrict__ out, const float* __restrict__ bias2, int n) {
    int gid = blockIdx.x * blockDim.x + threadIdx.x;
    if (gid >= n * OUTC) return;
    int nn = gid >> 6;
    int c = gid & (OUTC - 1);
    float wself = __expf(lrelu(g_as2[nn] + g_ad2[nn]));
    float denom = g_esum2[nn] + wself;
    out[gid] = (g_acc2[gid] + wself * g_h2[gid]) / denom + bias2[c];
}

// ---------------- launcher -----------------------------------------------------
extern "C" void kernel_launch(void* const* d_in, const int* in_sizes, int n_in,
                              void* d_out, int out_size) {
    const float* x     = (const float*)d_in[0];
    const int*   ei    = (const int*)  d_in[1];
    const float* W1    = (const float*)d_in[2];
    const float* as1   = (const float*)d_in[3];
    const float* ad1   = (const float*)d_in[4];
    const float* b1    = (const float*)d_in[5];
    const float* gamma = (const float*)d_in[6];
    const float* beta  = (const float*)d_in[7];
    const float* W2    = (const float*)d_in[8];
    const float* as2   = (const float*)d_in[9];
    const float* ad2   = (const float*)d_in[10];
    const float* b2    = (const float*)d_in[11];
    float* out = (float*)d_out;

    int n = in_sizes[0] / IN_DIM;
    int E = in_sizes[1] / 2;
    const int* srcp = ei;
    const int* dstp = ei + E;

    void* p;
    cudaGetSymbolAddress(&p, g_acc1);  cudaMemsetAsync(p, 0, (size_t)n * F1 * sizeof(float));
    cudaGetSymbolAddress(&p, g_esum1); cudaMemsetAsync(p, 0, (size_t)n * NHEADS * sizeof(float));
    cudaGetSymbolAddress(&p, g_acc2);  cudaMemsetAsync(p, 0, (size_t)n * OUTC * sizeof(float));
    cudaGetSymbolAddress(&p, g_esum2); cudaMemsetAsync(p, 0, (size_t)n * sizeof(float));

    k_fold<<<1, 128>>>(W1, as1, ad1, W2, as2, ad2);
    k1_proj<<<(n + 7) / 8, 256>>>(x, W1, n);
    {
        long long threads = (long long)E * 32;
        k2_edge1<<<(unsigned)((threads + 255) / 256), 256>>>(srcp, dstp, E);
    }
    k3_finalize1<<<n, 128>>>(b1, gamma, beta);
    k4_proj2<<<(n + 15) / 16, 256>>>(W2, n);
    {
        long long threads = (long long)E * 16;
        k5_edge2<<<(unsigned)((threads + 255) / 256), 256>>>(srcp, dstp, E);
    }
    k6_finalize2<<<(n * OUTC + 255) / 256, 256>>>(out, b2, n);
}

// round 2
// speedup vs baseline: 3.2022x; 3.2022x over previous
#include <cuda_runtime.h>
#include <cuda_fp16.h>

#define N_NODES 100000
#define E_EDGES 1600000
#define IN_DIM 32
#define HID 64
#define NHEADS 2
#define F1 128   // NHEADS*HID
#define OUTC 64

// ---------------- scratch (device globals; no allocation allowed) ------------
__device__ __align__(16) __half g_h1h [(size_t)N_NODES * F1];   // 25.6 MB
__device__ __align__(16) __half g_hlnh[(size_t)N_NODES * F1];   // 25.6 MB
__device__ __align__(16) __half g_h2h [(size_t)N_NODES * OUTC]; // 12.8 MB
__device__ float g_as1[N_NODES * NHEADS];
__device__ float g_ad1[N_NODES * NHEADS];
__device__ float g_as2[N_NODES];
__device__ float g_ad2[N_NODES];
__device__ int   g_deg[N_NODES];
__device__ int   g_off[N_NODES];
__device__ int   g_cur[N_NODES];
__device__ int   g_csr[E_EDGES];
__device__ int   g_bsum[256];
__device__ int   g_bscan[256];
__device__ float g_was1[IN_DIM * NHEADS];
__device__ float g_wad1[IN_DIM * NHEADS];
__device__ float g_was2[F1];
__device__ float g_wad2[F1];

__device__ __forceinline__ float lrelu(float v) { return v > 0.f ? v : 0.2f * v; }

// ---------------- fold attention vectors into the linear weights -------------
__global__ void k_fold(const float* __restrict__ W1,
                       const float* __restrict__ as1, const float* __restrict__ ad1,
                       const float* __restrict__ W2,
                       const float* __restrict__ as2, const float* __restrict__ ad2) {
    int t = threadIdx.x;  // 128 threads
    if (t < IN_DIM * NHEADS) {
        int k = t & (IN_DIM - 1), h = t >> 5;
        float s = 0.f, d = 0.f;
        for (int c = 0; c < HID; ++c) {
            float w = W1[k * F1 + h * HID + c];
            s += w * as1[h * HID + c];
            d += w * ad1[h * HID + c];
        }
        g_was1[k * NHEADS + h] = s;
        g_wad1[k * NHEADS + h] = d;
    }
    if (t < F1) {
        float s = 0.f, d = 0.f;
        for (int c = 0; c < OUTC; ++c) {
            float w = W2[t * OUTC + c];
            s += w * as2[c];
            d += w * ad2[c];
        }
        g_was2[t] = s;
        g_wad2[t] = d;
    }
}

// ---------------- CSR build ---------------------------------------------------
__global__ void k_deg(const int* __restrict__ dst, int E) {
    int e = blockIdx.x * blockDim.x + threadIdx.x;
    if (e < E) atomicAdd(&g_deg[dst[e]], 1);
}

// phase A: per-block (1024 elems) totals
__global__ void k_scanA(int n) {
    __shared__ int wsum[8];
    int t = threadIdx.x;                 // 256
    int base = blockIdx.x * 1024;
    int s = 0;
    #pragma unroll
    for (int i = 0; i < 4; ++i) {
        int idx = base + t * 4 + i;
        if (idx < n) s += g_deg[idx];
    }
    #pragma unroll
    for (int o = 16; o > 0; o >>= 1) s += __shfl_xor_sync(0xffffffffu, s, o);
    if ((t & 31) == 0) wsum[t >> 5] = s;
    __syncthreads();
    if (t == 0) {
        int tot = 0;
        #pragma unroll
        for (int i = 0; i < 8; ++i) tot += wsum[i];
        g_bsum[blockIdx.x] = tot;
    }
}

// phase B: exclusive scan of block totals (single block, nb <= 128)
__global__ void k_scanB(int nb) {
    __shared__ int ws[4];
    int t = threadIdx.x;                 // 128
    int v = (t < nb) ? g_bsum[t] : 0;
    int lane = t & 31, w = t >> 5;
    int s = v;
    #pragma unroll
    for (int o = 1; o < 32; o <<= 1) {
        int x = __shfl_up_sync(0xffffffffu, s, o);
        if (lane >= o) s += x;
    }
    if (lane == 31) ws[w] = s;
    __syncthreads();
    if (t < 4) {
        int x = ws[t];
        #pragma unroll
        for (int o = 1; o < 4; o <<= 1) {
            int y = __shfl_up_sync(0xfu, x, o);
            if (t >= o) x += y;
        }
        ws[t] = x;
    }
    __syncthreads();
    int incl = s + (w > 0 ? ws[w - 1] : 0);
    if (t < nb) g_bscan[t] = incl - v;
}

// phase C: full exclusive scan -> g_off (start) and g_cur (cursor)
__global__ void k_scanC(int n) {
    __shared__ int wsum[8];
    int t = threadIdx.x;                 // 256
    int base = blockIdx.x * 1024;
    int v[4]; int s = 0;
    #pragma unroll
    for (int i = 0; i < 4; ++i) {
        int idx = base + t * 4 + i;
        v[i] = (idx < n) ? g_deg[idx] : 0;
        s += v[i];
    }
    int lane = t & 31, w = t >> 5;
    int incl = s;
    #pragma unroll
    for (int o = 1; o < 32; o <<= 1) {
        int x = __shfl_up_sync(0xffffffffu, incl, o);
        if (lane >= o) incl += x;
    }
    if (lane == 31) wsum[w] = incl;
    __syncthreads();
    if (t < 8) {
        int x = wsum[t];
        #pragma unroll
        for (int o = 1; o < 8; o <<= 1) {
            int y = __shfl_up_sync(0xffu, x, o);
            if (t >= o) x += y;
        }
        wsum[t] = x;
    }
    __syncthreads();
    int excl = incl - s + (w > 0 ? wsum[w - 1] : 0) + g_bscan[blockIdx.x];
    #pragma unroll
    for (int i = 0; i < 4; ++i) {
        int idx = base + t * 4 + i;
        if (idx < n) { g_off[idx] = excl; g_cur[idx] = excl; excl += v[i]; }
    }
}

__global__ void k_scatter(const int* __restrict__ src, const int* __restrict__ dst, int E) {
    int e = blockIdx.x * blockDim.x + threadIdx.x;
    if (e >= E) return;
    int d = dst[e];
    int pos = atomicAdd(&g_cur[d], 1);
    g_csr[pos] = src[e];
}

// ---------------- layer-1 projection: h1(fp16) = x @ W1, plus logits ---------
__global__ void k1_proj(const float* __restrict__ x, const float* __restrict__ W1, int n) {
    __shared__ float Ws[IN_DIM * F1];          // 16 KB
    __shared__ float xsT[IN_DIM][33];          // 32 nodes, padded
    int t = threadIdx.x;                       // 256
    for (int i = t; i < IN_DIM * F1; i += 256) Ws[i] = W1[i];
    int base = blockIdx.x * 32;
    #pragma unroll
    for (int i = 0; i < 4; ++i) {
        int idx = t + i * 256;
        int node = idx >> 5, k = idx & 31;
        int nn = base + node;
        xsT[k][node] = (nn < n) ? x[(size_t)nn * IN_DIM + k] : 0.f;
    }
    __syncthreads();
    int tx = t & 31;        // col group: cols tx*4 .. tx*4+3
    int ty = t >> 5;        // node group: nodes ty*4 .. ty*4+3
    float acc[4][4] = {};
    #pragma unroll
    for (int k = 0; k < IN_DIM; ++k) {
        float4 wv = *(const float4*)&Ws[k * F1 + tx * 4];
        #pragma unroll
        for (int i = 0; i < 4; ++i) {
            float xv = xsT[k][ty * 4 + i];
            acc[i][0] += xv * wv.x;
            acc[i][1] += xv * wv.y;
            acc[i][2] += xv * wv.z;
            acc[i][3] += xv * wv.w;
        }
    }
    #pragma unroll
    for (int i = 0; i < 4; ++i) {
        int nn = base + ty * 4 + i;
        if (nn >= n) continue;
        __half2* hp = (__half2*)(g_h1h + (size_t)nn * F1 + tx * 4);
        hp[0] = __floats2half2_rn(acc[i][0], acc[i][1]);
        hp[1] = __floats2half2_rn(acc[i][2], acc[i][3]);
    }
    // layer-1 logits: a_s = x @ was1, a_d = x @ wad1
    if (t < 128) {
        int node = t >> 2, sel = t & 3;
        int nn = base + node;
        if (nn < n) {
            const float* fv = (sel < 2) ? g_was1 : g_wad1;
            int h = sel & 1;
            float a = 0.f;
            #pragma unroll
            for (int k = 0; k < IN_DIM; ++k) a += xsT[k][node] * fv[k * NHEADS + h];
            if (sel < 2) g_as1[nn * 2 + h] = a;
            else         g_ad1[nn * 2 + h] = a;
        }
    }
}

// ------- layer-1 gather + normalize + LN + ReLU + layer-2 logits (fused) -----
__global__ void k_gather1(const float* __restrict__ bias1,
                          const float* __restrict__ gamma,
                          const float* __restrict__ beta, int n) {
    int node = (blockIdx.x * blockDim.x + threadIdx.x) >> 5;
    if (node >= n) return;
    int lane = threadIdx.x & 31;
    float lad0 = g_ad1[2 * node], lad1 = g_ad1[2 * node + 1];
    float a0 = 0.f, a1 = 0.f, a2 = 0.f, a3 = 0.f, s0 = 0.f, s1 = 0.f;
    // self-loop
    {
        float w0 = __expf(lrelu(g_as1[2 * node] + lad0));
        float w1 = __expf(lrelu(g_as1[2 * node + 1] + lad1));
        const __half2* hp = (const __half2*)(g_h1h + (size_t)node * F1);
        float2 fa = __half22float2(hp[lane]);
        float2 fb = __half22float2(hp[lane + 32]);
        a0 += w0 * fa.x; a1 += w0 * fa.y; a2 += w1 * fb.x; a3 += w1 * fb.y;
        s0 += w0; s1 += w1;
    }
    int beg = g_off[node], end = g_cur[node];
    int srcN = (beg < end) ? g_csr[beg] : 0;
    for (int e = beg; e < end; ++e) {
        int src = srcN;
        if (e + 1 < end) srcN = g_csr[e + 1];
        float w0 = __expf(lrelu(g_as1[2 * src] + lad0));
        float w1 = __expf(lrelu(g_as1[2 * src + 1] + lad1));
        const __half2* hp = (const __half2*)(g_h1h + (size_t)src * F1);
        float2 fa = __half22float2(hp[lane]);
        float2 fb = __half22float2(hp[lane + 32]);
        a0 += w0 * fa.x; a1 += w0 * fa.y; a2 += w1 * fb.x; a3 += w1 * fb.y;
        s0 += w0; s1 += w1;
    }
    int c0 = 2 * lane, c2 = 2 * lane + 64;
    float r0 = 1.f / s0, r1 = 1.f / s1;
    float v0 = a0 * r0 + bias1[c0];
    float v1 = a1 * r0 + bias1[c0 + 1];
    float v2 = a2 * r1 + bias1[c2];
    float v3 = a3 * r1 + bias1[c2 + 1];
    // LayerNorm over 128 channels (warp holds 4/lane)
    float tot = v0 + v1 + v2 + v3;
    #pragma unroll
    for (int o = 16; o > 0; o >>= 1) tot += __shfl_xor_sync(0xffffffffu, tot, o);
    float mu = tot * (1.f / 128.f);
    float d0 = v0 - mu, d1 = v1 - mu, d2 = v2 - mu, d3 = v3 - mu;
    float sq = d0 * d0 + d1 * d1 + d2 * d2 + d3 * d3;
    #pragma unroll
    for (int o = 16; o > 0; o >>= 1) sq += __shfl_xor_sync(0xffffffffu, sq, o);
    float inv = rsqrtf(sq * (1.f / 128.f) + 1e-5f);
    float y0 = d0 * inv * gamma[c0]     + beta[c0];
    float y1 = d1 * inv * gamma[c0 + 1] + beta[c0 + 1];
    float y2 = d2 * inv * gamma[c2]     + beta[c2];
    float y3 = d3 * inv * gamma[c2 + 1] + beta[c2 + 1];
    y0 = fmaxf(y0, 0.f); y1 = fmaxf(y1, 0.f); y2 = fmaxf(y2, 0.f); y3 = fmaxf(y3, 0.f);
    __half2* op = (__half2*)(g_hlnh + (size_t)node * F1);
    op[lane]      = __floats2half2_rn(y0, y1);
    op[lane + 32] = __floats2half2_rn(y2, y3);
    // layer-2 logits from registers
    float sa = y0 * g_was2[c0] + y1 * g_was2[c0 + 1] + y2 * g_was2[c2] + y3 * g_was2[c2 + 1];
    float sd = y0 * g_wad2[c0] + y1 * g_wad2[c0 + 1] + y2 * g_wad2[c2] + y3 * g_wad2[c2 + 1];
    #pragma unroll
    for (int o = 16; o > 0; o >>= 1) {
        sa += __shfl_xor_sync(0xffffffffu, sa, o);
        sd += __shfl_xor_sync(0xffffffffu, sd, o);
    }
    if (lane == 0) { g_as2[node] = sa; g_ad2[node] = sd; }
}

// ---------------- layer-2 projection: h2(fp16) = hln @ W2 --------------------
__global__ void k4_proj(const float* __restrict__ W2, int n) {
    __shared__ float Ws[F1 * OUTC];            // 32 KB
    __shared__ __half2 xsT[F1 / 2][33];        // 64 x 33 half2 = 8.4 KB
    int t = threadIdx.x;                       // 128
    for (int i = t; i < F1 * OUTC; i += 128) Ws[i] = W2[i];
    int base = blockIdx.x * 32;
    #pragma unroll
    for (int i = 0; i < 16; ++i) {
        int idx = t + i * 128;
        int node = idx >> 6, kk = idx & 63;
        int nn = base + node;
        xsT[kk][node] = (nn < n) ? ((const __half2*)g_hlnh)[(size_t)nn * 64 + kk]
                                 : __float2half2_rn(0.f);
    }
    __syncthreads();
    int tx = t & 15;   // cols tx*4 .. +3
    int ty = t >> 4;   // nodes ty*4 .. +3
    float acc[4][4] = {};
    #pragma unroll 8
    for (int kk = 0; kk < 64; ++kk) {
        float4 wA = *(const float4*)&Ws[(2 * kk)     * OUTC + tx * 4];
        float4 wB = *(const float4*)&Ws[(2 * kk + 1) * OUTC + tx * 4];
        #pragma unroll
        for (int i = 0; i < 4; ++i) {
            float2 f = __half22float2(xsT[kk][ty * 4 + i]);
            acc[i][0] += f.x * wA.x + f.y * wB.x;
            acc[i][1] += f.x * wA.y + f.y * wB.y;
            acc[i][2] += f.x * wA.z + f.y * wB.z;
            acc[i][3] += f.x * wA.w + f.y * wB.w;
        }
    }
    #pragma unroll
    for (int i = 0; i < 4; ++i) {
        int nn = base + ty * 4 + i;
        if (nn >= n) continue;
        __half2* hp = (__half2*)(g_h2h + (size_t)nn * OUTC + tx * 4);
        hp[0] = __floats2half2_rn(acc[i][0], acc[i][1]);
        hp[1] = __floats2half2_rn(acc[i][2], acc[i][3]);
    }
}

// ---------------- layer-2 gather + finalize ----------------------------------
__global__ void k_gather2(float* __restrict__ out, const float* __restrict__ bias2, int n) {
    int node = (blockIdx.x * blockDim.x + threadIdx.x) >> 5;
    if (node >= n) return;
    int lane = threadIdx.x & 31;
    float lad = g_ad2[node];
    float ax = 0.f, ay = 0.f, ssum = 0.f;
    {
        float w = __expf(lrelu(g_as2[node] + lad));
        float2 f = __half22float2(((const __half2*)(g_h2h + (size_t)node * OUTC))[lane]);
        ax += w * f.x; ay += w * f.y; ssum += w;
    }
    int beg = g_off[node], end = g_cur[node];
    int srcN = (beg < end) ? g_csr[beg] : 0;
    for (int e = beg; e < end; ++e) {
        int src = srcN;
        if (e + 1 < end) srcN = g_csr[e + 1];
        float w = __expf(lrelu(g_as2[src] + lad));
        float2 f = __half22float2(((const __half2*)(g_h2h + (size_t)src * OUTC))[lane]);
        ax += w * f.x; ay += w * f.y; ssum += w;
    }
    float r = 1.f / ssum;
    float2 o;
    o.x = ax * r + bias2[2 * lane];
    o.y = ay * r + bias2[2 * lane + 1];
    ((float2*)out)[(size_t)node * 32 + lane] = o;
}

// ---------------- launcher -----------------------------------------------------
extern "C" void kernel_launch(void* const* d_in, const int* in_sizes, int n_in,
                              void* d_out, int out_size) {
    const float* x     = (const float*)d_in[0];
    const int*   ei    = (const int*)  d_in[1];
    const float* W1    = (const float*)d_in[2];
    const float* as1   = (const float*)d_in[3];
    const float* ad1   = (const float*)d_in[4];
    const float* b1    = (const float*)d_in[5];
    const float* gamma = (const float*)d_in[6];
    const float* beta  = (const float*)d_in[7];
    const float* W2    = (const float*)d_in[8];
    const float* as2   = (const float*)d_in[9];
    const float* ad2   = (const float*)d_in[10];
    const float* b2    = (const float*)d_in[11];
    float* out = (float*)d_out;

    int n = in_sizes[0] / IN_DIM;
    int E = in_sizes[1] / 2;
    const int* srcp = ei;
    const int* dstp = ei + E;
    int nb = (n + 1023) / 1024;

    void* p;
    cudaGetSymbolAddress(&p, g_deg);
    cudaMemsetAsync(p, 0, (size_t)n * sizeof(int));

    // CSR build
    k_deg<<<(E + 255) / 256, 256>>>(dstp, E);
    k_scanA<<<nb, 256>>>(n);
    k_scanB<<<1, 128>>>(nb);
    k_scanC<<<nb, 256>>>(n);
    k_scatter<<<(E + 255) / 256, 256>>>(srcp, dstp, E);

    // compute
    k_fold<<<1, 128>>>(W1, as1, ad1, W2, as2, ad2);
    k1_proj<<<(n + 31) / 32, 256>>>(x, W1, n);
    k_gather1<<<(n + 7) / 8, 256>>>(b1, gamma, beta, n);
    k4_proj<<<(n + 31) / 32, 128>>>(W2, n);
    k_gather2<<<(n + 7) / 8, 256>>>(out, b2, n);
}